// round 1
// baseline (speedup 1.0000x reference)
#include <cuda_runtime.h>
#include <cstdint>
#include <cstddef>

// ---------------------------------------------------------------------------
// MiniBatchKMeans: N=262144 points x D=64, K=1024 clusters.
// Output layout (float32): [assignments (262144)][counts (1024)][sums (1024*64)]
//
// Pipeline per launch (all graph-capturable, no allocs):
//   1. zero_kernel  : zero counts+sums region of d_out
//   2. csq_kernel   : per-centroid squared norms into __device__ g_csq
//   3. assign_kernel: 128x128-tiled fp32 GEMM (packed f32x2 FFMA) computing
//                     argmin_k (||c_k||^2 - 2 x.c_k), writes assignments,
//                     then fused scatter-add of point rows via red.global.add.v4.f32
// ---------------------------------------------------------------------------

#define N_POINTS   262144
#define DIMS       64
#define K_CLUSTERS 1024

#define OUT_ASSIGN 0
#define OUT_COUNTS (N_POINTS)
#define OUT_SUMS   (N_POINTS + K_CLUSTERS)

#define BM   128
#define BN   128
#define LDSU 132   // padded smem row stride (floats); 132%4==0 keeps float4 alignment

__device__ float g_csq[K_CLUSTERS];

typedef unsigned long long u64;

// ---- packed f32x2 helpers (ptxas will not auto-fuse; must be explicit PTX) ----
__device__ __forceinline__ u64 pack2(float lo, float hi) {
    u64 r;
    asm("mov.b64 %0, {%1,%2};" : "=l"(r) : "f"(lo), "f"(hi));
    return r;
}
__device__ __forceinline__ u64 fma2(u64 a, u64 b, u64 c) {
    u64 d;
    asm("fma.rn.f32x2 %0, %1, %2, %3;" : "=l"(d) : "l"(a), "l"(b), "l"(c));
    return d;
}
__device__ __forceinline__ void unpack2(u64 v, float& lo, float& hi) {
    asm("mov.b64 {%0,%1}, %2;" : "=f"(lo), "=f"(hi) : "l"(v));
}
// 128-bit vector reduction (sm_90+)
__device__ __forceinline__ void red_add_v4(float* p, float4 v) {
    asm volatile("red.global.add.v4.f32 [%0], {%1,%2,%3,%4};"
                 :: "l"(p), "f"(v.x), "f"(v.y), "f"(v.z), "f"(v.w) : "memory");
}

// ---------------------------------------------------------------------------
__global__ void zero_kernel(float* __restrict__ out) {
    int i = blockIdx.x * blockDim.x + threadIdx.x;
    const int n = K_CLUSTERS + K_CLUSTERS * DIMS;
    if (i < n) out[OUT_COUNTS + i] = 0.0f;
}

__global__ void csq_kernel(const float* __restrict__ cents) {
    int c = blockIdx.x * blockDim.x + threadIdx.x;
    if (c < K_CLUSTERS) {
        const float4* r = (const float4*)(cents + (size_t)c * DIMS);
        float s = 0.0f;
#pragma unroll
        for (int i = 0; i < 16; i++) {
            float4 v = r[i];
            s = fmaf(v.x, v.x, fmaf(v.y, v.y, fmaf(v.z, v.z, fmaf(v.w, v.w, s))));
        }
        g_csq[c] = s;
    }
}

// ---------------------------------------------------------------------------
extern __shared__ float smem[];

__global__ __launch_bounds__(256, 2)
void assign_kernel(const float* __restrict__ batch,
                   const float* __restrict__ cents,
                   float* __restrict__ out) {
    // smem carve: As[64][132] | Bs[64][132] | csq[128] | assign[128]
    float* As       = smem;
    float* Bs       = smem + 64 * LDSU;
    float* s_csq    = smem + 2 * 64 * LDSU;
    int*   s_assign = (int*)(s_csq + BN);
    // reduction arrays alias the As region (only used after compute finishes)
    float* red_v = As;                       // 128*17 floats
    int*   red_i = (int*)(As + 128 * 17);    // 128*17 ints (total 4352 < 8448)

    const int tid = threadIdx.x;
    const int tx  = tid & 15;
    const int ty  = tid >> 4;
    const int m0  = blockIdx.x * BM;

    // ---- load A tile (points), transposed to k-major: As[k][m] ----
    {
        const int r = tid >> 1, h = tid & 1;
        const float4* src = (const float4*)(batch + (size_t)(m0 + r) * DIMS);
#pragma unroll
        for (int c4 = 0; c4 < 8; c4++) {
            const int c = h * 8 + c4;
            float4 v = src[c];
            As[(4 * c + 0) * LDSU + r] = v.x;
            As[(4 * c + 1) * LDSU + r] = v.y;
            As[(4 * c + 2) * LDSU + r] = v.z;
            As[(4 * c + 3) * LDSU + r] = v.w;
        }
    }

    float minv[8];
    int   mini[8];
#pragma unroll
    for (int i = 0; i < 8; i++) { minv[i] = 3.4028235e38f; mini[i] = 0; }

    for (int chunk = 0; chunk < K_CLUSTERS / BN; chunk++) {
        const int n0 = chunk * BN;
        __syncthreads();   // protect Bs from previous chunk's readers
        {
            const int r = tid >> 1, h = tid & 1;
            const float4* src = (const float4*)(cents + (size_t)(n0 + r) * DIMS);
#pragma unroll
            for (int c4 = 0; c4 < 8; c4++) {
                const int c = h * 8 + c4;
                float4 v = src[c];
                Bs[(4 * c + 0) * LDSU + r] = v.x;
                Bs[(4 * c + 1) * LDSU + r] = v.y;
                Bs[(4 * c + 2) * LDSU + r] = v.z;
                Bs[(4 * c + 3) * LDSU + r] = v.w;
            }
            if (tid < BN) s_csq[tid] = g_csq[n0 + tid];
        }
        __syncthreads();

        // ---- 8x8 microtile GEMM, accumulators packed f32x2 along N ----
        u64 acc[8][4];
#pragma unroll
        for (int i = 0; i < 8; i++)
#pragma unroll
            for (int j = 0; j < 4; j++) acc[i][j] = 0ull;

#pragma unroll 8
        for (int k = 0; k < DIMS; k++) {
            const float4 b0 = *(const float4*)&Bs[k * LDSU + tx * 8];
            const float4 b1 = *(const float4*)&Bs[k * LDSU + tx * 8 + 4];
            u64 bb[4];
            bb[0] = pack2(b0.x, b0.y); bb[1] = pack2(b0.z, b0.w);
            bb[2] = pack2(b1.x, b1.y); bb[3] = pack2(b1.z, b1.w);
            const float4 a0 = *(const float4*)&As[k * LDSU + ty * 8];
            const float4 a1 = *(const float4*)&As[k * LDSU + ty * 8 + 4];
            const float av[8] = {a0.x, a0.y, a0.z, a0.w, a1.x, a1.y, a1.z, a1.w};
#pragma unroll
            for (int i = 0; i < 8; i++) {
                const u64 aa = pack2(av[i], av[i]);
#pragma unroll
                for (int j = 0; j < 4; j++)
                    acc[i][j] = fma2(aa, bb[j], acc[i][j]);
            }
        }

        // ---- epilogue: dist = csq - 2*cross, running argmin (first-min ties) ----
#pragma unroll
        for (int i = 0; i < 8; i++) {
#pragma unroll
            for (int j = 0; j < 4; j++) {
                float c0, c1;
                unpack2(acc[i][j], c0, c1);
                const int n = tx * 8 + 2 * j;
                const float d0 = fmaf(-2.0f, c0, s_csq[n]);
                const float d1 = fmaf(-2.0f, c1, s_csq[n + 1]);
                if (d0 < minv[i]) { minv[i] = d0; mini[i] = n0 + n; }
                if (d1 < minv[i]) { minv[i] = d1; mini[i] = n0 + n + 1; }
            }
        }
    }

    // ---- cross-thread argmin reduction (16 tx threads share each row) ----
    __syncthreads();
#pragma unroll
    for (int i = 0; i < 8; i++) {
        const int row = ty * 8 + i;
        red_v[row * 17 + tx] = minv[i];
        red_i[row * 17 + tx] = mini[i];
    }
    __syncthreads();
    if (tid < BM) {
        float bv = red_v[tid * 17];
        int   bi = red_i[tid * 17];
#pragma unroll
        for (int t = 1; t < 16; t++) {
            const float v  = red_v[tid * 17 + t];
            const int   ix = red_i[tid * 17 + t];
            if (v < bv || (v == bv && ix < bi)) { bv = v; bi = ix; }
        }
        s_assign[tid] = bi;
        out[OUT_ASSIGN + m0 + tid] = (float)bi;
    }
    __syncthreads();

    // ---- fused scatter: counts + per-dim sums via 128-bit vector reductions ----
    {
        const int p = tid >> 1, h = tid & 1;
        const int a = s_assign[p];
        const float4* src = (const float4*)(batch + (size_t)(m0 + p) * DIMS);
        float* dst = out + OUT_SUMS + (size_t)a * DIMS;
#pragma unroll
        for (int c4 = 0; c4 < 8; c4++) {
            const int c = h * 8 + c4;
            float4 v = src[c];
            red_add_v4(dst + c * 4, v);
        }
        if (h == 0) atomicAdd(out + OUT_COUNTS + a, 1.0f);
    }
}

// ---------------------------------------------------------------------------
extern "C" void kernel_launch(void* const* d_in, const int* in_sizes, int n_in,
                              void* d_out, int out_size) {
    const float* batch = (const float*)d_in[0];
    const float* cents = (const float*)d_in[1];
    float* out = (float*)d_out;

    const size_t SMEM_BYTES = (size_t)(2 * 64 * LDSU + BN) * sizeof(float)
                            + (size_t)BM * sizeof(int);
    cudaFuncSetAttribute(assign_kernel,
                         cudaFuncAttributeMaxDynamicSharedMemorySize,
                         (int)SMEM_BYTES);

    const int zero_n = K_CLUSTERS + K_CLUSTERS * DIMS;
    zero_kernel<<<(zero_n + 255) / 256, 256>>>(out);
    csq_kernel<<<(K_CLUSTERS + 255) / 256, 256>>>(cents);
    assign_kernel<<<N_POINTS / BM, 256, SMEM_BYTES>>>(batch, cents, out);
}